// round 2
// baseline (speedup 1.0000x reference)
#include <cuda_runtime.h>
#include <math.h>

// ---------------- scratch (device globals, no allocation) ----------------
__device__ float g_assign[8 * 64 * 1600];   // [b][k][n]
__device__ float g_vlad[8 * 32768];         // [b][d][k]  (== desc layout)
__device__ float g_cscale[8 * 64];          // combined intra-norm * 1/gnorm scale per (b,k)

#define EPSN 1e-12f

// ---------------- zero vlad ----------------
__global__ void k_zero() {
    int i = blockIdx.x * blockDim.x + threadIdx.x;
    if (i < 8 * 32768) g_vlad[i] = 0.0f;
}

// ---------------- scores GEMM + softmax over K ----------------
// grid (25, 8): n-tile of 64, batch. block 256 = 16x16.
__global__ __launch_bounds__(256) void k_scores(const float* __restrict__ x,
                                                const float* __restrict__ cw) {
    const int b = blockIdx.y;
    const int n0 = blockIdx.x * 64;

    __shared__ __align__(16) float cs[32][68];  // [dd][kk] (transposed conv chunk)
    __shared__ __align__(16) float fs[32][68];  // [dd][nn]
    __shared__ __align__(16) float sm[64][65];  // scores [k][n]
    __shared__ float inv_sum[64];

    const int tx = threadIdx.x & 15;   // n group
    const int ty = threadIdx.x >> 4;   // k group

    float acc[4][4];
#pragma unroll
    for (int i = 0; i < 4; i++)
#pragma unroll
        for (int j = 0; j < 4; j++) acc[i][j] = 0.0f;

    const float* xb = x + (size_t)b * 512 * 1600;

    for (int d0 = 0; d0 < 512; d0 += 32) {
        __syncthreads();
        // conv_w[k][d0+dd] -> cs[dd][k]
        for (int idx = threadIdx.x; idx < 2048; idx += 256) {
            int k = idx >> 5, dd = idx & 31;
            cs[dd][k] = cw[k * 512 + d0 + dd];
        }
        // x[b][d0+dd][n0+nn] -> fs[dd][nn]
        for (int idx = threadIdx.x; idx < 2048; idx += 256) {
            int dd = idx >> 6, nn = idx & 63;
            fs[dd][nn] = xb[(size_t)(d0 + dd) * 1600 + n0 + nn];
        }
        __syncthreads();
#pragma unroll 8
        for (int dd = 0; dd < 32; dd++) {
            float4 a = *(const float4*)&cs[dd][ty * 4];
            float4 f = *(const float4*)&fs[dd][tx * 4];
            acc[0][0] += a.x * f.x; acc[0][1] += a.x * f.y; acc[0][2] += a.x * f.z; acc[0][3] += a.x * f.w;
            acc[1][0] += a.y * f.x; acc[1][1] += a.y * f.y; acc[1][2] += a.y * f.z; acc[1][3] += a.y * f.w;
            acc[2][0] += a.z * f.x; acc[2][1] += a.z * f.y; acc[2][2] += a.z * f.z; acc[2][3] += a.z * f.w;
            acc[3][0] += a.w * f.x; acc[3][1] += a.w * f.y; acc[3][2] += a.w * f.z; acc[3][3] += a.w * f.w;
        }
    }
    __syncthreads();
#pragma unroll
    for (int i = 0; i < 4; i++)
#pragma unroll
        for (int j = 0; j < 4; j++) sm[ty * 4 + i][tx * 4 + j] = acc[i][j];
    __syncthreads();

    // softmax over k, one thread per n column
    if (threadIdx.x < 64) {
        const int n = threadIdx.x;
        float mx = -1e30f;
#pragma unroll 8
        for (int k = 0; k < 64; k++) mx = fmaxf(mx, sm[k][n]);
        float s = 0.0f;
#pragma unroll 8
        for (int k = 0; k < 64; k++) {
            float e = __expf(sm[k][n] - mx);
            sm[k][n] = e;
            s += e;
        }
        inv_sum[n] = 1.0f / s;
    }
    __syncthreads();

    float* ab = g_assign + (size_t)b * 64 * 1600 + n0;
    for (int idx = threadIdx.x; idx < 4096; idx += 256) {
        int k = idx >> 6, nn = idx & 63;
        ab[(size_t)k * 1600 + nn] = sm[k][nn] * inv_sum[nn];
    }
}

// ---------------- VLAD GEMM (partial over n-split) + centers term ----------------
// grid (5, 8, 8): n-split (320 n each), d-tile (64), batch. block 256 = 16x16.
__global__ __launch_bounds__(256) void k_vlad(const float* __restrict__ x,
                                              const float* __restrict__ centers) {
    const int b = blockIdx.z;
    const int d0 = blockIdx.y * 64;
    const int n0 = blockIdx.x * 320;

    __shared__ __align__(16) float fs[64][68];   // [nn][dd]
    __shared__ __align__(16) float as_[64][68];  // [nn][kk]
    __shared__ float asum_s[64];

    const int tx = threadIdx.x & 15;  // k group
    const int ty = threadIdx.x >> 4;  // d group

    float acc[4][4];
#pragma unroll
    for (int i = 0; i < 4; i++)
#pragma unroll
        for (int j = 0; j < 4; j++) acc[i][j] = 0.0f;
    float asum_acc = 0.0f;

    const float* xb = x + (size_t)b * 512 * 1600;
    const float* ab = g_assign + (size_t)b * 64 * 1600;

    for (int c = 0; c < 5; c++) {
        const int nb = n0 + c * 64;
        __syncthreads();
        for (int idx = threadIdx.x; idx < 4096; idx += 256) {
            int dd = idx >> 6, nn = idx & 63;
            fs[nn][dd] = xb[(size_t)(d0 + dd) * 1600 + nb + nn];
        }
        for (int idx = threadIdx.x; idx < 4096; idx += 256) {
            int kk = idx >> 6, nn = idx & 63;
            as_[nn][kk] = ab[(size_t)kk * 1600 + nb + nn];
        }
        __syncthreads();
#pragma unroll 8
        for (int nn = 0; nn < 64; nn++) {
            float4 f = *(const float4*)&fs[nn][ty * 4];
            float4 a = *(const float4*)&as_[nn][tx * 4];
            acc[0][0] += f.x * a.x; acc[0][1] += f.x * a.y; acc[0][2] += f.x * a.z; acc[0][3] += f.x * a.w;
            acc[1][0] += f.y * a.x; acc[1][1] += f.y * a.y; acc[1][2] += f.y * a.z; acc[1][3] += f.y * a.w;
            acc[2][0] += f.z * a.x; acc[2][1] += f.z * a.y; acc[2][2] += f.z * a.z; acc[2][3] += f.z * a.w;
            acc[3][0] += f.w * a.x; acc[3][1] += f.w * a.y; acc[3][2] += f.w * a.z; acc[3][3] += f.w * a.w;
        }
        if (threadIdx.x < 64) {
#pragma unroll 8
            for (int nn = 0; nn < 64; nn++) asum_acc += as_[nn][threadIdx.x];
        }
    }
    if (threadIdx.x < 64) asum_s[threadIdx.x] = asum_acc;
    __syncthreads();

    float* vb = g_vlad + (size_t)b * 32768;
#pragma unroll
    for (int i = 0; i < 4; i++) {
        const int d = d0 + ty * 4 + i;
#pragma unroll
        for (int j = 0; j < 4; j++) {
            const int k = tx * 4 + j;
            float v = acc[i][j] - asum_s[k] * centers[d * 64 + k];
            atomicAdd(&vb[d * 64 + k], v);
        }
    }
}

// ---------------- intra-norm + global norm -> combined scale ----------------
// grid 8 (batch), block 512 = 64 k x 8 dy
__global__ __launch_bounds__(512) void k_norm() {
    const int b = blockIdx.x;
    const int kx = threadIdx.x & 63;
    const int dy = threadIdx.x >> 6;
    const float* vb = g_vlad + (size_t)b * 32768;

    float ss = 0.0f;
    for (int d = dy; d < 512; d += 8) {
        float v = vb[d * 64 + kx];
        ss += v * v;
    }
    __shared__ float red[8][64];
    __shared__ float invs[64];
    __shared__ float contrib[64];
    __shared__ float ginv;
    red[dy][kx] = ss;
    __syncthreads();
    if (dy == 0) {
        float t = 0.0f;
#pragma unroll
        for (int r = 0; r < 8; r++) t += red[r][kx];
        float nrm = sqrtf(t);
        float inv = 1.0f / fmaxf(nrm, EPSN);
        invs[kx] = inv;
        contrib[kx] = t * inv * inv;
    }
    __syncthreads();
    if (threadIdx.x == 0) {
        float g = 0.0f;
#pragma unroll
        for (int k = 0; k < 64; k++) g += contrib[k];
        ginv = 1.0f / fmaxf(sqrtf(g), EPSN);
    }
    __syncthreads();
    if (dy == 0) g_cscale[b * 64 + kx] = invs[kx] * ginv;
}

// ---------------- whitening GEMM (the HBM kernel) ----------------
// grid 128, block 256 (8 warps x 4 output rows each = 32 rows/block)
__global__ __launch_bounds__(256) void k_whiten(const float* __restrict__ W,
                                                const float* __restrict__ bias,
                                                float* __restrict__ out) {
    __shared__ __align__(16) float dsc[8][1024];  // b-major desc tile (scaled)

    const int lane = threadIdx.x & 31;
    const int warp = threadIdx.x >> 5;
    const int o0 = blockIdx.x * 32 + warp * 4;

    float acc[4][8];
#pragma unroll
    for (int r = 0; r < 4; r++)
#pragma unroll
        for (int bb = 0; bb < 8; bb++) acc[r][bb] = 0.0f;

    const float4* vlad4 = (const float4*)g_vlad;

    for (int jt = 0; jt < 32768; jt += 1024) {
        __syncthreads();
        // stage scaled desc tile, float4, conflict-free
        for (int idx = threadIdx.x; idx < 2048; idx += 256) {
            int bb = idx >> 8;        // batch
            int q = idx & 255;        // float4 index within 1024-float row
            int j4 = (jt >> 2) + q;   // global float4 index within batch row
            float4 v = vlad4[bb * 8192 + j4];
            float4 c = *(const float4*)&g_cscale[bb * 64 + ((j4 & 15) << 2)];
            float4 r4;
            r4.x = v.x * c.x; r4.y = v.y * c.y; r4.z = v.z * c.z; r4.w = v.w * c.w;
            *(float4*)&dsc[bb][q << 2] = r4;
        }
        __syncthreads();

        const float* Wp = W + (size_t)o0 * 32768 + jt;
#pragma unroll
        for (int s = 0; s < 8; s++) {
            const int jj = s * 128 + lane * 4;
            float4 w0 = *(const float4*)(Wp + jj);
            float4 w1 = *(const float4*)(Wp + 32768 + jj);
            float4 w2 = *(const float4*)(Wp + 65536 + jj);
            float4 w3 = *(const float4*)(Wp + 98304 + jj);
#pragma unroll
            for (int bb = 0; bb < 8; bb++) {
                float4 d = *(const float4*)&dsc[bb][jj];
                acc[0][bb] += w0.x * d.x + w0.y * d.y + w0.z * d.z + w0.w * d.w;
                acc[1][bb] += w1.x * d.x + w1.y * d.y + w1.z * d.z + w1.w * d.w;
                acc[2][bb] += w2.x * d.x + w2.y * d.y + w2.z * d.z + w2.w * d.w;
                acc[3][bb] += w3.x * d.x + w3.y * d.y + w3.z * d.z + w3.w * d.w;
            }
        }
    }

    // butterfly reduce each accumulator over the warp
#pragma unroll
    for (int r = 0; r < 4; r++)
#pragma unroll
        for (int bb = 0; bb < 8; bb++)
#pragma unroll
            for (int off = 16; off; off >>= 1)
                acc[r][bb] += __shfl_xor_sync(0xffffffffu, acc[r][bb], off);

    const int r = lane >> 3;
    const int bsel = lane & 7;
    float res = 0.0f;
#pragma unroll
    for (int rr = 0; rr < 4; rr++)
#pragma unroll
        for (int bb = 0; bb < 8; bb++)
            if (rr == r && bb == bsel) res = acc[rr][bb];

    out[bsel * 4096 + o0 + r] = res + bias[o0 + r];
}

// ---------------- final per-row L2 norm (in place) ----------------
__global__ __launch_bounds__(256) void k_final(float* __restrict__ out) {
    const int b = blockIdx.x;
    float* ob = out + (size_t)b * 4096;
    float v[16];
    float ss = 0.0f;
#pragma unroll
    for (int t = 0; t < 16; t++) {
        v[t] = ob[threadIdx.x + t * 256];
        ss += v[t] * v[t];
    }
#pragma unroll
    for (int off = 16; off; off >>= 1) ss += __shfl_xor_sync(0xffffffffu, ss, off);
    __shared__ float r[8];
    __shared__ float sc;
    const int lane = threadIdx.x & 31, warp = threadIdx.x >> 5;
    if (lane == 0) r[warp] = ss;
    __syncthreads();
    if (threadIdx.x == 0) {
        float t = 0.0f;
#pragma unroll
        for (int i = 0; i < 8; i++) t += r[i];
        sc = 1.0f / fmaxf(sqrtf(t), EPSN);
    }
    __syncthreads();
#pragma unroll
    for (int t = 0; t < 16; t++) ob[threadIdx.x + t * 256] = v[t] * sc;
}

// ---------------- launch ----------------
extern "C" void kernel_launch(void* const* d_in, const int* in_sizes, int n_in,
                              void* d_out, int out_size) {
    const float* x        = (const float*)d_in[0];
    const float* conv_w   = (const float*)d_in[1];
    const float* centers  = (const float*)d_in[2];
    const float* whiten_w = (const float*)d_in[3];
    const float* whiten_b = (const float*)d_in[4];
    float* out = (float*)d_out;

    k_zero<<<1024, 256>>>();
    k_scores<<<dim3(25, 8), 256>>>(x, conv_w);
    k_vlad<<<dim3(5, 8, 8), 256>>>(x, centers);
    k_norm<<<8, 512>>>();
    k_whiten<<<128, 256>>>(whiten_w, whiten_b, out);
    k_final<<<8, 256>>>(out);
}

// round 3
// speedup vs baseline: 1.2077x; 1.2077x over previous
#include <cuda_runtime.h>
#include <math.h>

// ---------------- scratch (device globals, no allocation) ----------------
__device__ float g_assign[8 * 64 * 1600];        // [b][k][n]
__device__ float g_vpart[5 * 8 * 32768];         // [nsplit][b][d*64+k] vlad partials
__device__ float g_vlad[8 * 32768];              // [b][d][k] summed + PRE-SCALED desc

#define EPSN 1e-12f

// packed fp32x2 FMA: acc = a*b + acc (elementwise on two packed floats)
__device__ __forceinline__ void ffma2(unsigned long long& acc,
                                      unsigned long long a,
                                      unsigned long long b) {
    asm("fma.rn.f32x2 %0, %1, %2, %0;" : "+l"(acc) : "l"(a), "l"(b));
}

// ---------------- scores GEMM + softmax over K ----------------
// grid (25, 8): n-tile of 64, batch. block 256 = 16x16.
__global__ __launch_bounds__(256) void k_scores(const float* __restrict__ x,
                                                const float* __restrict__ cw) {
    const int b = blockIdx.y;
    const int n0 = blockIdx.x * 64;

    __shared__ __align__(16) float cs[32][68];  // [dd][kk]
    __shared__ __align__(16) float fs[32][68];  // [dd][nn]
    __shared__ __align__(16) float sm[64][65];  // scores [k][n]
    __shared__ float inv_sum[64];

    const int tx = threadIdx.x & 15;   // n group
    const int ty = threadIdx.x >> 4;   // k group

    float acc[4][4];
#pragma unroll
    for (int i = 0; i < 4; i++)
#pragma unroll
        for (int j = 0; j < 4; j++) acc[i][j] = 0.0f;

    const float* xb = x + (size_t)b * 512 * 1600;

    for (int d0 = 0; d0 < 512; d0 += 32) {
        __syncthreads();
        for (int idx = threadIdx.x; idx < 2048; idx += 256) {
            int k = idx >> 5, dd = idx & 31;
            cs[dd][k] = cw[k * 512 + d0 + dd];
        }
        for (int idx = threadIdx.x; idx < 2048; idx += 256) {
            int dd = idx >> 6, nn = idx & 63;
            fs[dd][nn] = xb[(size_t)(d0 + dd) * 1600 + n0 + nn];
        }
        __syncthreads();
#pragma unroll 8
        for (int dd = 0; dd < 32; dd++) {
            float4 a = *(const float4*)&cs[dd][ty * 4];
            float4 f = *(const float4*)&fs[dd][tx * 4];
            acc[0][0] += a.x * f.x; acc[0][1] += a.x * f.y; acc[0][2] += a.x * f.z; acc[0][3] += a.x * f.w;
            acc[1][0] += a.y * f.x; acc[1][1] += a.y * f.y; acc[1][2] += a.y * f.z; acc[1][3] += a.y * f.w;
            acc[2][0] += a.z * f.x; acc[2][1] += a.z * f.y; acc[2][2] += a.z * f.z; acc[2][3] += a.z * f.w;
            acc[3][0] += a.w * f.x; acc[3][1] += a.w * f.y; acc[3][2] += a.w * f.z; acc[3][3] += a.w * f.w;
        }
    }
    __syncthreads();
#pragma unroll
    for (int i = 0; i < 4; i++)
#pragma unroll
        for (int j = 0; j < 4; j++) sm[ty * 4 + i][tx * 4 + j] = acc[i][j];
    __syncthreads();

    if (threadIdx.x < 64) {
        const int n = threadIdx.x;
        float mx = -1e30f;
#pragma unroll 8
        for (int k = 0; k < 64; k++) mx = fmaxf(mx, sm[k][n]);
        float s = 0.0f;
#pragma unroll 8
        for (int k = 0; k < 64; k++) {
            float e = __expf(sm[k][n] - mx);
            sm[k][n] = e;
            s += e;
        }
        inv_sum[n] = 1.0f / s;
    }
    __syncthreads();

    float* ab = g_assign + (size_t)b * 64 * 1600 + n0;
    for (int idx = threadIdx.x; idx < 4096; idx += 256) {
        int k = idx >> 6, nn = idx & 63;
        ab[(size_t)k * 1600 + nn] = sm[k][nn] * inv_sum[nn];
    }
}

// ---------------- VLAD GEMM (partial over n-split) + centers term ----------------
// grid (5, 8, 8): n-split (320 n each), d-tile (64), batch. block 256 = 16x16.
// Writes straight to g_vpart[nsplit] -- no atomics, no zero-fill needed.
__global__ __launch_bounds__(256) void k_vlad(const float* __restrict__ x,
                                              const float* __restrict__ centers) {
    const int b = blockIdx.z;
    const int d0 = blockIdx.y * 64;
    const int n0 = blockIdx.x * 320;

    __shared__ __align__(16) float fs[64][68];   // [nn][dd]
    __shared__ __align__(16) float as_[64][68];  // [nn][kk]
    __shared__ float asum_s[64];

    const int tx = threadIdx.x & 15;  // k group
    const int ty = threadIdx.x >> 4;  // d group

    float acc[4][4];
#pragma unroll
    for (int i = 0; i < 4; i++)
#pragma unroll
        for (int j = 0; j < 4; j++) acc[i][j] = 0.0f;
    float asum_acc = 0.0f;

    const float* xb = x + (size_t)b * 512 * 1600;
    const float* ab = g_assign + (size_t)b * 64 * 1600;

    for (int c = 0; c < 5; c++) {
        const int nb = n0 + c * 64;
        __syncthreads();
        for (int idx = threadIdx.x; idx < 4096; idx += 256) {
            int dd = idx >> 6, nn = idx & 63;
            fs[nn][dd] = xb[(size_t)(d0 + dd) * 1600 + nb + nn];
        }
        for (int idx = threadIdx.x; idx < 4096; idx += 256) {
            int kk = idx >> 6, nn = idx & 63;
            as_[nn][kk] = ab[(size_t)kk * 1600 + nb + nn];
        }
        __syncthreads();
#pragma unroll 8
        for (int nn = 0; nn < 64; nn++) {
            float4 f = *(const float4*)&fs[nn][ty * 4];
            float4 a = *(const float4*)&as_[nn][tx * 4];
            acc[0][0] += f.x * a.x; acc[0][1] += f.x * a.y; acc[0][2] += f.x * a.z; acc[0][3] += f.x * a.w;
            acc[1][0] += f.y * a.x; acc[1][1] += f.y * a.y; acc[1][2] += f.y * a.z; acc[1][3] += f.y * a.w;
            acc[2][0] += f.z * a.x; acc[2][1] += f.z * a.y; acc[2][2] += f.z * a.z; acc[2][3] += f.z * a.w;
            acc[3][0] += f.w * a.x; acc[3][1] += f.w * a.y; acc[3][2] += f.w * a.z; acc[3][3] += f.w * a.w;
        }
        if (threadIdx.x < 64) {
#pragma unroll 8
            for (int nn = 0; nn < 64; nn++) asum_acc += as_[nn][threadIdx.x];
        }
    }
    if (threadIdx.x < 64) asum_s[threadIdx.x] = asum_acc;
    __syncthreads();

    float* vb = g_vpart + ((size_t)blockIdx.x * 8 + b) * 32768;
#pragma unroll
    for (int i = 0; i < 4; i++) {
        const int d = d0 + ty * 4 + i;
#pragma unroll
        for (int j = 0; j < 4; j++) {
            const int k = tx * 4 + j;
            vb[d * 64 + k] = acc[i][j] - asum_s[k] * centers[d * 64 + k];
        }
    }
}

// ---------------- sum partials + intra-norm + global norm + PRE-SCALE ----------------
// grid 8 (batch), block 512 = 64 k x 8 dy
__global__ __launch_bounds__(512) void k_norm() {
    const int b = blockIdx.x;
    const int kx = threadIdx.x & 63;
    const int dy = threadIdx.x >> 6;
    float* vb = g_vlad + (size_t)b * 32768;

    // pass 1: sum 5 partials -> g_vlad, accumulate per-k sum of squares
    float ss = 0.0f;
    for (int d = dy; d < 512; d += 8) {
        const int i = d * 64 + kx;
        float v = 0.0f;
#pragma unroll
        for (int s = 0; s < 5; s++) v += g_vpart[((size_t)s * 8 + b) * 32768 + i];
        vb[i] = v;
        ss += v * v;
    }

    __shared__ float red[8][64];
    __shared__ float cs_s[64];
    __shared__ float contrib[64];
    __shared__ float ginv;
    red[dy][kx] = ss;
    __syncthreads();
    if (dy == 0) {
        float t = 0.0f;
#pragma unroll
        for (int r = 0; r < 8; r++) t += red[r][kx];
        float inv = 1.0f / fmaxf(sqrtf(t), EPSN);
        cs_s[kx] = inv;
        contrib[kx] = t * inv * inv;
    }
    __syncthreads();
    if (threadIdx.x == 0) {
        float g = 0.0f;
#pragma unroll
        for (int k = 0; k < 64; k++) g += contrib[k];
        ginv = 1.0f / fmaxf(sqrtf(g), EPSN);
    }
    __syncthreads();

    // pass 2: scale in place (L2-hot)
    const float sc = cs_s[kx] * ginv;
    for (int d = dy; d < 512; d += 8) vb[d * 64 + kx] *= sc;
}

// ---------------- whitening GEMM (the HBM kernel) ----------------
// grid 128, block 256 (8 warps x 4 output rows = 32 rows/block).
// FFMA2 (fma.rn.f32x2) + double-buffered W prefetch; desc already pre-scaled.
__global__ __launch_bounds__(256) void k_whiten(const float* __restrict__ W,
                                                const float* __restrict__ bias,
                                                float* __restrict__ out) {
    __shared__ __align__(16) float dsc[8][1024];  // b-major desc tile

    const int lane = threadIdx.x & 31;
    const int warp = threadIdx.x >> 5;
    const int o0 = blockIdx.x * 32 + warp * 4;

    unsigned long long acc2[4][8];
#pragma unroll
    for (int r = 0; r < 4; r++)
#pragma unroll
        for (int bb = 0; bb < 8; bb++) acc2[r][bb] = 0ULL;

    const float4* __restrict__ vlad4 = (const float4*)g_vlad;

    for (int jt = 0; jt < 32768; jt += 1024) {
        __syncthreads();
        for (int idx = threadIdx.x; idx < 2048; idx += 256) {
            int bb = idx >> 8;
            int q = idx & 255;
            *(float4*)&dsc[bb][q << 2] = vlad4[bb * 8192 + (jt >> 2) + q];
        }
        __syncthreads();

        const float* Wp = W + (size_t)o0 * 32768 + jt;
        ulonglong2 wbuf[2][4];
#pragma unroll
        for (int r = 0; r < 4; r++)
            wbuf[0][r] = *(const ulonglong2*)(Wp + (size_t)r * 32768 + lane * 4);

#pragma unroll
        for (int s = 0; s < 8; s++) {
            const int cur = s & 1;
            if (s < 7) {
                const int jn = (s + 1) * 128 + lane * 4;
#pragma unroll
                for (int r = 0; r < 4; r++)
                    wbuf[cur ^ 1][r] = *(const ulonglong2*)(Wp + (size_t)r * 32768 + jn);
            }
            const int jj = s * 128 + lane * 4;
#pragma unroll
            for (int bb = 0; bb < 8; bb++) {
                ulonglong2 d = *(const ulonglong2*)&dsc[bb][jj];
#pragma unroll
                for (int r = 0; r < 4; r++) {
                    ffma2(acc2[r][bb], wbuf[cur][r].x, d.x);
                    ffma2(acc2[r][bb], wbuf[cur][r].y, d.y);
                }
            }
        }
    }

    // collapse packed halves, butterfly-reduce across warp
    float accf[4][8];
#pragma unroll
    for (int r = 0; r < 4; r++)
#pragma unroll
        for (int bb = 0; bb < 8; bb++) {
            float2 f = *reinterpret_cast<float2*>(&acc2[r][bb]);
            float v = f.x + f.y;
#pragma unroll
            for (int off = 16; off; off >>= 1)
                v += __shfl_xor_sync(0xffffffffu, v, off);
            accf[r][bb] = v;
        }

    const int r = lane >> 3;
    const int bsel = lane & 7;
    float res = 0.0f;
#pragma unroll
    for (int rr = 0; rr < 4; rr++)
#pragma unroll
        for (int bb = 0; bb < 8; bb++)
            if (rr == r && bb == bsel) res = accf[rr][bb];

    out[bsel * 4096 + o0 + r] = res + bias[o0 + r];
}

// ---------------- final per-row L2 norm (in place) ----------------
__global__ __launch_bounds__(256) void k_final(float* __restrict__ out) {
    const int b = blockIdx.x;
    float* ob = out + (size_t)b * 4096;
    float v[16];
    float ss = 0.0f;
#pragma unroll
    for (int t = 0; t < 16; t++) {
        v[t] = ob[threadIdx.x + t * 256];
        ss += v[t] * v[t];
    }
#pragma unroll
    for (int off = 16; off; off >>= 1) ss += __shfl_xor_sync(0xffffffffu, ss, off);
    __shared__ float r[8];
    __shared__ float sc;
    const int lane = threadIdx.x & 31, warp = threadIdx.x >> 5;
    if (lane == 0) r[warp] = ss;
    __syncthreads();
    if (threadIdx.x == 0) {
        float t = 0.0f;
#pragma unroll
        for (int i = 0; i < 8; i++) t += r[i];
        sc = 1.0f / fmaxf(sqrtf(t), EPSN);
    }
    __syncthreads();
#pragma unroll
    for (int t = 0; t < 16; t++) ob[threadIdx.x + t * 256] = v[t] * sc;
}

// ---------------- launch ----------------
extern "C" void kernel_launch(void* const* d_in, const int* in_sizes, int n_in,
                              void* d_out, int out_size) {
    const float* x        = (const float*)d_in[0];
    const float* conv_w   = (const float*)d_in[1];
    const float* centers  = (const float*)d_in[2];
    const float* whiten_w = (const float*)d_in[3];
    const float* whiten_b = (const float*)d_in[4];
    float* out = (float*)d_out;

    k_scores<<<dim3(25, 8), 256>>>(x, conv_w);
    k_vlad<<<dim3(5, 8, 8), 256>>>(x, centers);
    k_norm<<<8, 512>>>();
    k_whiten<<<128, 256>>>(whiten_w, whiten_b, out);
    k_final<<<8, 256>>>(out);
}